// round 10
// baseline (speedup 1.0000x reference)
#include <cuda_runtime.h>
#include <cuda_fp16.h>
#include <cstdint>

#define BATCH 8
#define HW    1024
#define QKV_CH 768

// Scratch (device globals; no allocation allowed)
__device__ __half g_xh    [BATCH * 512 * HW];   // x in fp16
__device__ __half g_wqkvh [QKV_CH * 512];       // w_qkv fp16
__device__ __half g_wattnh[512 * 256];          // w_attn fp16
__device__ __half g_qkvh  [BATCH * QKV_CH * HW];
__device__ __half g_afh   [BATCH * 256 * HW];   // attention out, scrambled layout

// ===========================================================================
// helpers
// ===========================================================================
__device__ __forceinline__ uint32_t smem_u32(const void* p) {
    uint32_t a;
    asm("{ .reg .u64 t; cvta.to.shared.u64 t, %1; cvt.u32.u64 %0, t; }"
        : "=r"(a) : "l"(p));
    return a;
}
__device__ __forceinline__ void mma16816(float* c, const uint32_t* a, const uint32_t* b) {
    asm volatile("mma.sync.aligned.m16n8k16.row.col.f32.f16.f16.f32 "
        "{%0,%1,%2,%3}, {%4,%5,%6,%7}, {%8,%9}, {%0,%1,%2,%3};"
        : "+f"(c[0]), "+f"(c[1]), "+f"(c[2]), "+f"(c[3])
        : "r"(a[0]), "r"(a[1]), "r"(a[2]), "r"(a[3]), "r"(b[0]), "r"(b[1]));
}
__device__ __forceinline__ void ldsm_x4(uint32_t* r, uint32_t addr) {
    asm volatile("ldmatrix.sync.aligned.m8n8.x4.shared.b16 {%0,%1,%2,%3}, [%4];"
        : "=r"(r[0]), "=r"(r[1]), "=r"(r[2]), "=r"(r[3]) : "r"(addr));
}
__device__ __forceinline__ void ldsm_x4t(uint32_t* r, uint32_t addr) {
    asm volatile("ldmatrix.sync.aligned.m8n8.x4.trans.shared.b16 {%0,%1,%2,%3}, [%4];"
        : "=r"(r[0]), "=r"(r[1]), "=r"(r[2]), "=r"(r[3]) : "r"(addr));
}
__device__ __forceinline__ uint32_t pack_h2(float lo, float hi) {
    __half2 h = __floats2half2_rn(lo, hi);
    return *reinterpret_cast<uint32_t*>(&h);
}
__device__ __forceinline__ uint32_t hh2pack(__half a, __half b) {
    __half2 h = __halves2half2(a, b);
    return *reinterpret_cast<uint32_t*>(&h);
}
__device__ __forceinline__ float2 h2f2(uint32_t u) {
    __half2 h = *reinterpret_cast<__half2*>(&u);
    return __half22float2(h);
}
#define CP_ASYNC16(dst, src) \
    asm volatile("cp.async.cg.shared.global [%0], [%1], 16;" \
                 :: "r"(dst), "l"(src) : "memory")
#define CP_COMMIT() asm volatile("cp.async.commit_group;" ::: "memory")
#define CP_WAIT1()  asm volatile("cp.async.wait_group 1;" ::: "memory")
#define GROUP_BAR128(id) asm volatile("bar.sync %0, 128;" :: "r"(id) : "memory")

// packed fp32x2
typedef unsigned long long ull;
__device__ __forceinline__ ull fma2v(ull a, ull b, ull c) {
    ull d; asm("fma.rn.f32x2 %0, %1, %2, %3;" : "=l"(d) : "l"(a), "l"(b), "l"(c)); return d;
}
__device__ __forceinline__ ull mul2v(ull a, ull b) {
    ull d; asm("mul.rn.f32x2 %0, %1, %2;" : "=l"(d) : "l"(a), "l"(b)); return d;
}
__device__ __forceinline__ ull add2v(ull a, ull b) {
    ull d; asm("add.rn.f32x2 %0, %1, %2;" : "=l"(d) : "l"(a), "l"(b)); return d;
}
__device__ __forceinline__ ull dup2(float v) {
    ull r; uint32_t u = __float_as_uint(v);
    asm("mov.b64 %0, {%1, %1};" : "=l"(r) : "r"(u));
    return r;
}
__device__ __forceinline__ ull pk2(float x, float y) {
    ull r; uint32_t a = __float_as_uint(x), b = __float_as_uint(y);
    asm("mov.b64 %0, {%1, %2};" : "=l"(r) : "r"(a), "r"(b));
    return r;
}
__device__ __forceinline__ float frcpa(float x) {
    float r; asm("rcp.approx.f32 %0, %1;" : "=f"(r) : "f"(x)); return r;
}
__device__ __forceinline__ void exp2pairf(ull l, float& elo, float& ehi) {
    const ull LOG2E2 = dup2(1.4426950408889634f);
    const ull MAGIC2 = dup2(12582912.0f);
    const ull NMAGIC2 = dup2(-12582912.0f);
    const ull NONE2  = dup2(-1.0f);
    ull y  = mul2v(l, LOG2E2);
    ull tt = add2v(y, MAGIC2);
    ull nn2 = add2v(tt, NMAGIC2);
    ull f  = fma2v(nn2, NONE2, y);
    ull pe = fma2v(dup2(9.6183290401232e-3f), f, dup2(5.550410866482158e-2f));
    pe = fma2v(pe, f, dup2(2.402265069591007e-1f));
    pe = fma2v(pe, f, dup2(6.931471805599453e-1f));
    pe = fma2v(pe, f, dup2(1.0f));
    uint32_t tlo, thi, plo, phi;
    asm("mov.b64 {%0,%1}, %2;" : "=r"(tlo), "=r"(thi) : "l"(tt));
    asm("mov.b64 {%0,%1}, %2;" : "=r"(plo), "=r"(phi) : "l"(pe));
    elo = __int_as_float((int)((tlo << 23) + plo));
    ehi = __int_as_float((int)((thi << 23) + phi));
}

// ===========================================================================
// fp32 -> fp16 conversion (elementwise, float4-granular)
// ===========================================================================
__global__ void f2h_kernel(const float* __restrict__ in, __half* __restrict__ out,
                           int n4)
{
    int i = blockIdx.x * blockDim.x + threadIdx.x;
    if (i < n4) {
        float4 v = ((const float4*)in)[i];
        uint2 p;
        p.x = pack_h2(v.x, v.y);
        p.y = pack_h2(v.z, v.w);
        ((uint2*)out)[i] = p;
    }
}

// ===========================================================================
// all-fp16 mma.sync GEMM, cp.async 3-stage: Y[b][m][n] = W[m][:]·X[b][:][n]+bias
// CTA tile 128x128, BK=32, 8 warps (2m x 4n), m16n8k16, ldmatrix fragments.
// ===========================================================================
static constexpr int GASZ = 128 * 80;     // A stage: [128 m][40 halves]
static constexpr int GBSZ = 32 * 272;     // B stage: [32 k][136 halves]
static constexpr int GSTG = GASZ + GBSZ;  // 18944
static constexpr int GEMM_SMEM = 3 * GSTG;

template<int M, int K, int SCALE_ROWS, typename TY>
__global__ __launch_bounds__(256)
void gemm_mma(const __half* __restrict__ W, const __half* __restrict__ X,
              const float* __restrict__ bias, TY* __restrict__ Y,
              float scaleVal)
{
    extern __shared__ char smraw[];
    const uint32_t smb = smem_u32(smraw);

    const int t    = threadIdx.x;
    const int lane = t & 31;
    const int wid  = t >> 5;
    const int g    = lane >> 2;
    const int t4   = lane & 3;
    const int wm   = (wid & 1) * 64;
    const int wn   = (wid >> 1) * 32;
    const int b    = blockIdx.z;
    const int m0   = blockIdx.y * 128;
    const int n0   = blockIdx.x * 128;
    const __half* Xb = X + (size_t)b * K * 1024;
    TY*           Yb = Y + (size_t)b * M * 1024;

    const int r16 = lane & 15;
    const int c8  = (lane >> 4) * 8;
    const uint32_t aAddr = smb + (wm + r16) * 80 + c8 * 2;
    const uint32_t bAddr = smb + GASZ + r16 * 272 + (wn + c8) * 2;

    const int NC = K / 32;
    auto PRE = [&](int kc) {
        if (kc < NC) {
            const uint32_t so = (uint32_t)(kc % 3) * GSTG;
#pragma unroll
            for (int c = 0; c < 2; c++) {
                int ch = c * 256 + t;
                int ar = ch >> 2, ac = (ch & 3) * 8;
                CP_ASYNC16(smb + so + ar * 80 + ac * 2,
                           W + (size_t)(m0 + ar) * K + kc * 32 + ac);
                int br = ch >> 4, bc = (ch & 15) * 8;
                CP_ASYNC16(smb + so + GASZ + br * 272 + bc * 2,
                           Xb + (size_t)(kc * 32 + br) * 1024 + n0 + bc);
            }
        }
        CP_COMMIT();
    };

    float acc[4][4][4];
#pragma unroll
    for (int i = 0; i < 4; i++)
#pragma unroll
        for (int j = 0; j < 4; j++)
#pragma unroll
            for (int q = 0; q < 4; q++) acc[i][j][q] = 0.f;

    PRE(0);
    PRE(1);

    for (int kc = 0; kc < NC; kc++) {
        CP_WAIT1();                 // group kc complete (kc+1 may be in flight)
        __syncthreads();            // all threads past compute(kc-1)
        PRE(kc + 2);                // writes (kc+2)%3 == (kc-1)%3: safe post-sync

        const uint32_t so = (uint32_t)(kc % 3) * GSTG;
        const uint32_t aB = aAddr + so;
        const uint32_t bB = bAddr + so;
#pragma unroll
        for (int s = 0; s < 2; s++) {
            uint32_t afr[4][4], bfr[2][4];
#pragma unroll
            for (int mf = 0; mf < 4; mf++)
                ldsm_x4(afr[mf], aB + mf * 16 * 80 + s * 32);
#pragma unroll
            for (int np = 0; np < 2; np++)
                ldsm_x4t(bfr[np], bB + np * 32 + s * 16 * 272);
#pragma unroll
            for (int mf = 0; mf < 4; mf++)
#pragma unroll
                for (int np = 0; np < 2; np++) {
                    mma16816(acc[mf][2 * np],     afr[mf], bfr[np] + 0);
                    mma16816(acc[mf][2 * np + 1], afr[mf], bfr[np] + 2);
                }
        }
    }

    // epilogue: bias (+ optional q scale)
#pragma unroll
    for (int mf = 0; mf < 4; mf++) {
        int r0 = m0 + wm + mf * 16 + g;
        int r1 = r0 + 8;
        float b0v = bias[r0], b1v = bias[r1];
        float s0 = (SCALE_ROWS > 0 && r0 < SCALE_ROWS) ? scaleVal : 1.f;
        float s1 = (SCALE_ROWS > 0 && r1 < SCALE_ROWS) ? scaleVal : 1.f;
#pragma unroll
        for (int nf = 0; nf < 4; nf++) {
            int nc = n0 + wn + nf * 8 + 2 * t4;
            if constexpr (sizeof(TY) == 2) {
                *(uint32_t*)&Yb[(size_t)r0 * 1024 + nc] =
                    pack_h2((acc[mf][nf][0] + b0v) * s0, (acc[mf][nf][1] + b0v) * s0);
                *(uint32_t*)&Yb[(size_t)r1 * 1024 + nc] =
                    pack_h2((acc[mf][nf][2] + b1v) * s1, (acc[mf][nf][3] + b1v) * s1);
            } else {
                float2 v0, v1;
                v0.x = (acc[mf][nf][0] + b0v) * s0;
                v0.y = (acc[mf][nf][1] + b0v) * s0;
                v1.x = (acc[mf][nf][2] + b1v) * s1;
                v1.y = (acc[mf][nf][3] + b1v) * s1;
                *(float2*)&Yb[(size_t)r0 * 1024 + nc] = v0;
                *(float2*)&Yb[(size_t)r1 * 1024 + nc] = v1;
            }
        }
    }
}

// ===========================================================================
// fp16 fused attention, in-register head softmax, 512 threads (16 warps =
// 4 q-groups x 4 head-pairs). Warp (qg, hp) owns queries [qt*64+qg*16, +16)
// and heads {2hp, 2hp+1}. Denominators: in-register over own 2 heads, then
// 4-warp exchange per q-group (smem + 128-thread named barrier). W repacked
// in-register as AV A-frags. K/V triple-buffered cp.async, ONE __syncthreads
// per tile. Softmax across the 8 HEADS (reference axis=1). Output: scrambled
// flat-reshape layout, fp16.
// ===========================================================================
static constexpr int KS_OFF = 0;                     // 3 x 20480
static constexpr int VS_OFF = 3 * 20480;             // 3 x 20480
static constexpr int PD_OFF = 6 * 20480;             // 16 x 2176
static constexpr int ATTN_SMEM = PD_OFF + 16 * 2176; // 157696

__global__ __launch_bounds__(512)
void attn_mma(const __half* __restrict__ qkvh, __half* __restrict__ af)
{
    extern __shared__ char smraw[];
    const uint32_t smb = smem_u32(smraw);

    const int b    = blockIdx.y;
    const int qt   = blockIdx.x;           // 16 tiles of 64 queries
    const int t    = threadIdx.x;
    const int lane = t & 31;
    const int w    = t >> 5;               // 16 warps
    const int qg   = w >> 2;               // q-group 0..3 (16 queries each)
    const int hp   = w & 3;                // head pair: heads 2hp, 2hp+1
    const int g    = lane >> 2;
    const int t4   = lane & 3;

    const int r16 = lane & 15;
    const int c8  = (lane >> 4) * 8;
    const int r2  = (lane & 7) + (lane >> 4) * 8;
    const int c2  = ((lane >> 3) & 1) * 8;

    const int qW = qt * 64 + qg * 16;
    const __half* qbh = qkvh + (size_t)b * QKV_CH * HW;

    // ---- preload Q A-fragments for 2 heads (reused all 32 tiles) ----
    uint32_t qa[2][2][4];
#pragma unroll
    for (int h = 0; h < 2; h++) {
        const int gh = hp * 2 + h;
#pragma unroll
        for (int s = 0; s < 2; s++) {
            int d0 = s * 16 + 2 * t4;
            const __half* ra = qbh + (size_t)(gh * 32 + d0) * HW;
            const __half* rb = qbh + (size_t)(gh * 32 + d0 + 1) * HW;
            const __half* rc = qbh + (size_t)(gh * 32 + d0 + 8) * HW;
            const __half* rd = qbh + (size_t)(gh * 32 + d0 + 9) * HW;
            int qq = qW + g;
            qa[h][s][0] = hh2pack(ra[qq],     rb[qq]);
            qa[h][s][1] = hh2pack(ra[qq + 8], rb[qq + 8]);
            qa[h][s][2] = hh2pack(rc[qq],     rd[qq]);
            qa[h][s][3] = hh2pack(rc[qq + 8], rd[qq + 8]);
        }
    }

    float oacc[2][4][4];
#pragma unroll
    for (int i = 0; i < 2; i++)
#pragma unroll
        for (int j = 0; j < 4; j++)
#pragma unroll
            for (int q = 0; q < 4; q++) oacc[i][j][q] = 0.f;

    const uint32_t kRow = smb + KS_OFF + r16 * 80 + c8 * 2;
    const uint32_t vRow = smb + VS_OFF + r2 * 80 + c2 * 2;
    char* pdW = smraw + PD_OFF + w * 2176;

    // prefetch one 32-wide k-tile (K + V) into buffer kt%3
    auto PREFETCH = [&](int kt2) {
        if (kt2 <= 31) {
            const int k0 = kt2 * 32;
            const int bo = (kt2 % 3) * 20480;
#pragma unroll
            for (int c = 0; c < 2; c++) {
                int idx = c * 512 + t;
                int row = idx >> 2;
                int col = (idx & 3) * 8;
                CP_ASYNC16(smb + KS_OFF + bo + row * 80 + col * 2,
                           qbh + (size_t)(256 + row) * HW + k0 + col);
                CP_ASYNC16(smb + VS_OFF + bo + row * 80 + col * 2,
                           qbh + (size_t)(512 + row) * HW + k0 + col);
            }
        }
        CP_COMMIT();
    };

    PREFETCH(0);

    for (int kt = 0; kt < 32; kt++) {
        PREFETCH(kt + 1);          // writes (kt+1)%3 == (kt-2)%3: readers done
        CP_WAIT1();                // own group kt landed
        __syncthreads();           // all groups kt visible; kt-1 readers done

        const uint32_t bo = (uint32_t)(kt % 3) * 20480;

        // ---- S + exp + in-register partial denominators (own 2 heads) ----
        uint32_t eh[2][4][2];
        float pd[16];
#pragma unroll
        for (int i = 0; i < 16; i++) pd[i] = 0.f;

#pragma unroll
        for (int h = 0; h < 2; h++) {
            const uint32_t kh = kRow + bo + (hp * 2 + h) * 2560;
            float sacc[4][4];
#pragma unroll
            for (int nf = 0; nf < 4; nf++)
#pragma unroll
                for (int q = 0; q < 4; q++) sacc[nf][q] = 0.f;
#pragma unroll
            for (int np = 0; np < 2; np++)
#pragma unroll
                for (int s = 0; s < 2; s++) {
                    uint32_t bk[4];
                    ldsm_x4t(bk, kh + s * 1280 + np * 32);
                    mma16816(sacc[np * 2 + 0], qa[h][s], bk + 0);
                    mma16816(sacc[np * 2 + 1], qa[h][s], bk + 2);
                }
#pragma unroll
            for (int nf = 0; nf < 4; nf++) {
                float e0, e1, e2, e3;
                exp2pairf(pk2(sacc[nf][0], sacc[nf][1]), e0, e1);
                exp2pairf(pk2(sacc[nf][2], sacc[nf][3]), e2, e3);
                pd[nf * 4 + 0] += e0;
                pd[nf * 4 + 1] += e1;
                pd[nf * 4 + 2] += e2;
                pd[nf * 4 + 3] += e3;
                eh[h][nf][0] = pack_h2(e0, e1);
                eh[h][nf][1] = pack_h2(e2, e3);
            }
        }

        // ---- 4-warp denominator exchange (only softmax sync) ----
#pragma unroll
        for (int nf = 0; nf < 4; nf++) {
            *(float2*)(pdW + ((g)     * 34 + nf * 8 + 2 * t4) * 4) =
                make_float2(pd[nf * 4 + 0], pd[nf * 4 + 1]);
            *(float2*)(pdW + ((g + 8) * 34 + nf * 8 + 2 * t4) * 4) =
                make_float2(pd[nf * 4 + 2], pd[nf * 4 + 3]);
        }
        GROUP_BAR128(1 + qg);
        float rcp[16];
#pragma unroll
        for (int nf = 0; nf < 4; nf++) {
            float s0x = pd[nf * 4 + 0], s0y = pd[nf * 4 + 1];
            float s1x = pd[nf * 4 + 2], s1y = pd[nf * 4 + 3];
#pragma unroll
            for (int j = 0; j < 4; j++) {
                if (j == hp) continue;
                char* pdP = smraw + PD_OFF + (qg * 4 + j) * 2176;
                float2 a0 = *(float2*)(pdP + ((g)     * 34 + nf * 8 + 2 * t4) * 4);
                float2 a1 = *(float2*)(pdP + ((g + 8) * 34 + nf * 8 + 2 * t4) * 4);
                s0x += a0.x; s0y += a0.y;
                s1x += a1.x; s1y += a1.y;
            }
            rcp[nf * 4 + 0] = frcpa(s0x);
            rcp[nf * 4 + 1] = frcpa(s0y);
            rcp[nf * 4 + 2] = frcpa(s1x);
            rcp[nf * 4 + 3] = frcpa(s1y);
        }

        // ---- O += W V (W repacked in-register; V from smem as B-frags) ----
#pragma unroll
        for (int h = 0; h < 2; h++) {
            const uint32_t vh = vRow + bo + (hp * 2 + h) * 2560;
#pragma unroll
            for (int ks = 0; ks < 2; ks++) {
                uint32_t wfrag[4];
                {
                    float2 f = h2f2(eh[h][2 * ks][0]);
                    wfrag[0] = pack_h2(f.x * rcp[8 * ks + 0], f.y * rcp[8 * ks + 1]);
                }
                {
                    float2 f = h2f2(eh[h][2 * ks][1]);
                    wfrag[1] = pack_h2(f.x * rcp[8 * ks + 2], f.y * rcp[8 * ks + 3]);
                }
                {
                    float2 f = h2f2(eh[h][2 * ks + 1][0]);
                    wfrag[2] = pack_h2(f.x * rcp[8 * ks + 4], f.y * rcp[8 * ks + 5]);
                }
                {
                    float2 f = h2f2(eh[h][2 * ks + 1][1]);
                    wfrag[3] = pack_h2(f.x * rcp[8 * ks + 6], f.y * rcp[8 * ks + 7]);
                }
#pragma unroll
                for (int db = 0; db < 2; db++) {
                    uint32_t vb[4];
                    ldsm_x4(vb, vh + db * 1280 + ks * 32);
                    mma16816(oacc[h][db * 2 + 0], wfrag, vb + 0);
                    mma16816(oacc[h][db * 2 + 1], wfrag, vb + 2);
                }
            }
        }
    }

    // ---- epilogue: scrambled flat-reshape layout, fp16 ----
    // AF row = b*256 + gh*32 + qt*2 + (qg>>1); col base = (qg&1)*512
#pragma unroll
    for (int h = 0; h < 2; h++) {
        const int gh = hp * 2 + h;
        __half* ob = af + ((size_t)(b * 256 + gh * 32 + qt * 2 + (qg >> 1))) * 1024
                     + (qg & 1) * 512;
#pragma unroll
        for (int nd = 0; nd < 4; nd++) {
#pragma unroll
            for (int rh = 0; rh < 2; rh++) {
                int col = (g + 8 * rh) * 32 + nd * 8 + 2 * t4;
                *(uint32_t*)(ob + col) =
                    pack_h2(oacc[h][nd][rh * 2 + 0], oacc[h][nd][rh * 2 + 1]);
            }
        }
    }
}

// ---------------------------------------------------------------------------
extern "C" void kernel_launch(void* const* d_in, const int* in_sizes, int n_in,
                              void* d_out, int out_size)
{
    const float* x      = (const float*)d_in[0];   // [8,512,32,32]
    const float* w_qkv  = (const float*)d_in[1];   // [768,512]
    const float* b_qkv  = (const float*)d_in[2];   // [768]
    const float* w_attn = (const float*)d_in[3];   // [512,256]
    const float* b_attn = (const float*)d_in[4];   // [512]
    float* out = (float*)d_out;                    // [8,512,32,32]

    void *xh, *wqh, *wah, *qkvp, *afp;
    cudaGetSymbolAddress(&xh,   g_xh);
    cudaGetSymbolAddress(&wqh,  g_wqkvh);
    cudaGetSymbolAddress(&wah,  g_wattnh);
    cudaGetSymbolAddress(&qkvp, g_qkvh);
    cudaGetSymbolAddress(&afp,  g_afh);

    cudaFuncSetAttribute((const void*)gemm_mma<768, 512, 256, __half>,
                         cudaFuncAttributeMaxDynamicSharedMemorySize, GEMM_SMEM);
    cudaFuncSetAttribute((const void*)gemm_mma<512, 256, 0, float>,
                         cudaFuncAttributeMaxDynamicSharedMemorySize, GEMM_SMEM);
    cudaFuncSetAttribute((const void*)attn_mma,
                         cudaFuncAttributeMaxDynamicSharedMemorySize, ATTN_SMEM);

    // 0) fp32 -> fp16 conversions (x, both weight matrices)
    f2h_kernel<<<(1048576 + 255) / 256, 256>>>(x, (__half*)xh, 1048576);
    f2h_kernel<<<(98304 + 255) / 256, 256>>>(w_qkv, (__half*)wqh, 98304);
    f2h_kernel<<<(32768 + 255) / 256, 256>>>(w_attn, (__half*)wah, 32768);

    // 1) QKV projection (all-fp16 mma; bias; q rows scaled; fp16 output)
    gemm_mma<768, 512, 256, __half><<<dim3(8, 6, BATCH), 256, GEMM_SMEM>>>(
        (const __half*)wqh, (const __half*)xh, b_qkv, (__half*)qkvp,
        0.17677669529663687f);

    // 2) fp16 fused attention, in-register head softmax, 512 threads
    attn_mma<<<dim3(16, BATCH), 512, ATTN_SMEM>>>((const __half*)qkvp,
                                                  (__half*)afp);

    // 3) output projection (all-fp16 mma; fp32 output)
    gemm_mma<512, 256, 0, float><<<dim3(8, 4, BATCH), 256, GEMM_SMEM>>>(
        (const __half*)wah, (const __half*)afp, b_attn, out, 1.0f);
}

// round 11
// speedup vs baseline: 1.4106x; 1.4106x over previous
#include <cuda_runtime.h>
#include <cuda_fp16.h>
#include <cstdint>

#define BATCH 8
#define HW    1024
#define QKV_CH 768

// Scratch (device globals; no allocation allowed)
__device__ __half g_xh    [BATCH * 512 * HW];   // x in fp16
__device__ __half g_wqkvh [QKV_CH * 512];       // w_qkv fp16
__device__ __half g_wattnh[512 * 256];          // w_attn fp16
__device__ __half g_qkvh  [BATCH * QKV_CH * HW];
__device__ __half g_afh   [BATCH * 256 * HW];   // attention out, scrambled layout

// ===========================================================================
// helpers
// ===========================================================================
__device__ __forceinline__ uint32_t smem_u32(const void* p) {
    uint32_t a;
    asm("{ .reg .u64 t; cvta.to.shared.u64 t, %1; cvt.u32.u64 %0, t; }"
        : "=r"(a) : "l"(p));
    return a;
}
__device__ __forceinline__ void mma16816(float* c, const uint32_t* a, const uint32_t* b) {
    asm volatile("mma.sync.aligned.m16n8k16.row.col.f32.f16.f16.f32 "
        "{%0,%1,%2,%3}, {%4,%5,%6,%7}, {%8,%9}, {%0,%1,%2,%3};"
        : "+f"(c[0]), "+f"(c[1]), "+f"(c[2]), "+f"(c[3])
        : "r"(a[0]), "r"(a[1]), "r"(a[2]), "r"(a[3]), "r"(b[0]), "r"(b[1]));
}
__device__ __forceinline__ void ldsm_x4(uint32_t* r, uint32_t addr) {
    asm volatile("ldmatrix.sync.aligned.m8n8.x4.shared.b16 {%0,%1,%2,%3}, [%4];"
        : "=r"(r[0]), "=r"(r[1]), "=r"(r[2]), "=r"(r[3]) : "r"(addr));
}
__device__ __forceinline__ void ldsm_x4t(uint32_t* r, uint32_t addr) {
    asm volatile("ldmatrix.sync.aligned.m8n8.x4.trans.shared.b16 {%0,%1,%2,%3}, [%4];"
        : "=r"(r[0]), "=r"(r[1]), "=r"(r[2]), "=r"(r[3]) : "r"(addr));
}
__device__ __forceinline__ uint32_t pack_h2(float lo, float hi) {
    __half2 h = __floats2half2_rn(lo, hi);
    return *reinterpret_cast<uint32_t*>(&h);
}
__device__ __forceinline__ uint32_t hh2pack(__half a, __half b) {
    __half2 h = __halves2half2(a, b);
    return *reinterpret_cast<uint32_t*>(&h);
}
__device__ __forceinline__ float2 h2f2(uint32_t u) {
    __half2 h = *reinterpret_cast<__half2*>(&u);
    return __half22float2(h);
}
#define CP_ASYNC16(dst, src) \
    asm volatile("cp.async.cg.shared.global [%0], [%1], 16;" \
                 :: "r"(dst), "l"(src) : "memory")
#define CP_COMMIT() asm volatile("cp.async.commit_group;" ::: "memory")
#define CP_WAIT1()  asm volatile("cp.async.wait_group 1;" ::: "memory")
#define GROUP_BAR64(id) asm volatile("bar.sync %0, 64;" :: "r"(id) : "memory")

// packed fp32x2
typedef unsigned long long ull;
__device__ __forceinline__ ull fma2v(ull a, ull b, ull c) {
    ull d; asm("fma.rn.f32x2 %0, %1, %2, %3;" : "=l"(d) : "l"(a), "l"(b), "l"(c)); return d;
}
__device__ __forceinline__ ull mul2v(ull a, ull b) {
    ull d; asm("mul.rn.f32x2 %0, %1, %2;" : "=l"(d) : "l"(a), "l"(b)); return d;
}
__device__ __forceinline__ ull add2v(ull a, ull b) {
    ull d; asm("add.rn.f32x2 %0, %1, %2;" : "=l"(d) : "l"(a), "l"(b)); return d;
}
__device__ __forceinline__ ull dup2(float v) {
    ull r; uint32_t u = __float_as_uint(v);
    asm("mov.b64 %0, {%1, %1};" : "=l"(r) : "r"(u));
    return r;
}
__device__ __forceinline__ ull pk2(float x, float y) {
    ull r; uint32_t a = __float_as_uint(x), b = __float_as_uint(y);
    asm("mov.b64 %0, {%1, %2};" : "=l"(r) : "r"(a), "r"(b));
    return r;
}
__device__ __forceinline__ float frcpa(float x) {
    float r; asm("rcp.approx.f32 %0, %1;" : "=f"(r) : "f"(x)); return r;
}
__device__ __forceinline__ void exp2pairf(ull l, float& elo, float& ehi) {
    const ull LOG2E2 = dup2(1.4426950408889634f);
    const ull MAGIC2 = dup2(12582912.0f);
    const ull NMAGIC2 = dup2(-12582912.0f);
    const ull NONE2  = dup2(-1.0f);
    ull y  = mul2v(l, LOG2E2);
    ull tt = add2v(y, MAGIC2);
    ull nn2 = add2v(tt, NMAGIC2);
    ull f  = fma2v(nn2, NONE2, y);
    ull pe = fma2v(dup2(9.6183290401232e-3f), f, dup2(5.550410866482158e-2f));
    pe = fma2v(pe, f, dup2(2.402265069591007e-1f));
    pe = fma2v(pe, f, dup2(6.931471805599453e-1f));
    pe = fma2v(pe, f, dup2(1.0f));
    uint32_t tlo, thi, plo, phi;
    asm("mov.b64 {%0,%1}, %2;" : "=r"(tlo), "=r"(thi) : "l"(tt));
    asm("mov.b64 {%0,%1}, %2;" : "=r"(plo), "=r"(phi) : "l"(pe));
    elo = __int_as_float((int)((tlo << 23) + plo));
    ehi = __int_as_float((int)((thi << 23) + phi));
}

// ===========================================================================
// fused fp32 -> fp16 conversion for x, w_qkv, w_attn (one launch)
// ===========================================================================
static constexpr int N4_X  = 1048576;   // 8*512*1024 / 4
static constexpr int N4_WQ = 98304;     // 768*512 / 4
static constexpr int N4_WA = 32768;     // 512*256 / 4
static constexpr int N4_ALL = N4_X + N4_WQ + N4_WA;

__global__ void f2h_all(const float* __restrict__ x, const float* __restrict__ wq,
                        const float* __restrict__ wa,
                        __half* __restrict__ xh, __half* __restrict__ wqh,
                        __half* __restrict__ wah)
{
    int i = blockIdx.x * blockDim.x + threadIdx.x;
    const float* src;
    __half* dst;
    int j;
    if (i < N4_X)                 { src = x;  dst = xh;  j = i; }
    else if (i < N4_X + N4_WQ)    { src = wq; dst = wqh; j = i - N4_X; }
    else if (i < N4_ALL)          { src = wa; dst = wah; j = i - N4_X - N4_WQ; }
    else return;
    float4 v = ((const float4*)src)[j];
    uint2 p;
    p.x = pack_h2(v.x, v.y);
    p.y = pack_h2(v.z, v.w);
    ((uint2*)dst)[j] = p;
}

// ===========================================================================
// all-fp16 mma.sync GEMM, cp.async 3-stage (R10, measured 31.1us on QKV)
// ===========================================================================
static constexpr int GASZ = 128 * 80;
static constexpr int GBSZ = 32 * 272;
static constexpr int GSTG = GASZ + GBSZ;
static constexpr int GEMM_SMEM = 3 * GSTG;

template<int M, int K, int SCALE_ROWS, typename TY>
__global__ __launch_bounds__(256)
void gemm_mma(const __half* __restrict__ W, const __half* __restrict__ X,
              const float* __restrict__ bias, TY* __restrict__ Y,
              float scaleVal)
{
    extern __shared__ char smraw[];
    const uint32_t smb = smem_u32(smraw);

    const int t    = threadIdx.x;
    const int lane = t & 31;
    const int wid  = t >> 5;
    const int g    = lane >> 2;
    const int t4   = lane & 3;
    const int wm   = (wid & 1) * 64;
    const int wn   = (wid >> 1) * 32;
    const int b    = blockIdx.z;
    const int m0   = blockIdx.y * 128;
    const int n0   = blockIdx.x * 128;
    const __half* Xb = X + (size_t)b * K * 1024;
    TY*           Yb = Y + (size_t)b * M * 1024;

    const int r16 = lane & 15;
    const int c8  = (lane >> 4) * 8;
    const uint32_t aAddr = smb + (wm + r16) * 80 + c8 * 2;
    const uint32_t bAddr = smb + GASZ + r16 * 272 + (wn + c8) * 2;

    const int NC = K / 32;
    auto PRE = [&](int kc) {
        if (kc < NC) {
            const uint32_t so = (uint32_t)(kc % 3) * GSTG;
#pragma unroll
            for (int c = 0; c < 2; c++) {
                int ch = c * 256 + t;
                int ar = ch >> 2, ac = (ch & 3) * 8;
                CP_ASYNC16(smb + so + ar * 80 + ac * 2,
                           W + (size_t)(m0 + ar) * K + kc * 32 + ac);
                int br = ch >> 4, bc = (ch & 15) * 8;
                CP_ASYNC16(smb + so + GASZ + br * 272 + bc * 2,
                           Xb + (size_t)(kc * 32 + br) * 1024 + n0 + bc);
            }
        }
        CP_COMMIT();
    };

    float acc[4][4][4];
#pragma unroll
    for (int i = 0; i < 4; i++)
#pragma unroll
        for (int j = 0; j < 4; j++)
#pragma unroll
            for (int q = 0; q < 4; q++) acc[i][j][q] = 0.f;

    PRE(0);
    PRE(1);

    for (int kc = 0; kc < NC; kc++) {
        CP_WAIT1();
        __syncthreads();
        PRE(kc + 2);

        const uint32_t so = (uint32_t)(kc % 3) * GSTG;
        const uint32_t aB = aAddr + so;
        const uint32_t bB = bAddr + so;
#pragma unroll
        for (int s = 0; s < 2; s++) {
            uint32_t afr[4][4], bfr[2][4];
#pragma unroll
            for (int mf = 0; mf < 4; mf++)
                ldsm_x4(afr[mf], aB + mf * 16 * 80 + s * 32);
#pragma unroll
            for (int np = 0; np < 2; np++)
                ldsm_x4t(bfr[np], bB + np * 32 + s * 16 * 272);
#pragma unroll
            for (int mf = 0; mf < 4; mf++)
#pragma unroll
                for (int np = 0; np < 2; np++) {
                    mma16816(acc[mf][2 * np],     afr[mf], bfr[np] + 0);
                    mma16816(acc[mf][2 * np + 1], afr[mf], bfr[np] + 2);
                }
        }
    }

#pragma unroll
    for (int mf = 0; mf < 4; mf++) {
        int r0 = m0 + wm + mf * 16 + g;
        int r1 = r0 + 8;
        float b0v = bias[r0], b1v = bias[r1];
        float s0 = (SCALE_ROWS > 0 && r0 < SCALE_ROWS) ? scaleVal : 1.f;
        float s1 = (SCALE_ROWS > 0 && r1 < SCALE_ROWS) ? scaleVal : 1.f;
#pragma unroll
        for (int nf = 0; nf < 4; nf++) {
            int nc = n0 + wn + nf * 8 + 2 * t4;
            if constexpr (sizeof(TY) == 2) {
                *(uint32_t*)&Yb[(size_t)r0 * 1024 + nc] =
                    pack_h2((acc[mf][nf][0] + b0v) * s0, (acc[mf][nf][1] + b0v) * s0);
                *(uint32_t*)&Yb[(size_t)r1 * 1024 + nc] =
                    pack_h2((acc[mf][nf][2] + b1v) * s1, (acc[mf][nf][3] + b1v) * s1);
            } else {
                float2 v0, v1;
                v0.x = (acc[mf][nf][0] + b0v) * s0;
                v0.y = (acc[mf][nf][1] + b0v) * s0;
                v1.x = (acc[mf][nf][2] + b1v) * s1;
                v1.y = (acc[mf][nf][3] + b1v) * s1;
                *(float2*)&Yb[(size_t)r0 * 1024 + nc] = v0;
                *(float2*)&Yb[(size_t)r1 * 1024 + nc] = v1;
            }
        }
    }
}

// ===========================================================================
// fp16 fused attention, in-register head softmax (R9 structure: 256 threads,
// 8 warps = 4 pairs x 16 q, 4 heads/warp, ~1 CTA/SM, NO register cap).
// Added vs R9: head-0 V fragments hoisted above the pair barrier so the
// scheduler has independent ldsm/mma work during the barrier + rcp window.
// Softmax across the 8 HEADS. Output: scrambled flat-reshape layout, fp16.
// ===========================================================================
static constexpr int KS_OFF = 0;                    // 3 x 20480
static constexpr int VS_OFF = 3 * 20480;            // 3 x 20480
static constexpr int PD_OFF = 6 * 20480;            // 8 x 2176
static constexpr int ATTN_SMEM = PD_OFF + 8 * 2176; // 140288 B

__global__ __launch_bounds__(256, 1)
void attn_mma(const __half* __restrict__ qkvh, __half* __restrict__ af)
{
    extern __shared__ char smraw[];
    const uint32_t smb = smem_u32(smraw);

    const int b    = blockIdx.y;
    const int qt   = blockIdx.x;           // 16 tiles of 64 queries
    const int t    = threadIdx.x;
    const int lane = t & 31;
    const int w    = t >> 5;               // 8 warps
    const int p    = w >> 1;               // pair 0..3
    const int wip  = w & 1;                // 0: heads 0-3, 1: heads 4-7
    const int g    = lane >> 2;
    const int t4   = lane & 3;

    const int r16 = lane & 15;
    const int c8  = (lane >> 4) * 8;
    const int r2  = (lane & 7) + (lane >> 4) * 8;
    const int c2  = ((lane >> 3) & 1) * 8;

    const int qW = qt * 64 + p * 16;       // this pair's 16-query slice
    const __half* qbh = qkvh + (size_t)b * QKV_CH * HW;

    // ---- preload Q A-fragments for 4 heads (reused all 32 tiles) ----
    uint32_t qa[4][2][4];
#pragma unroll
    for (int h = 0; h < 4; h++) {
        const int gh = wip * 4 + h;
#pragma unroll
        for (int s = 0; s < 2; s++) {
            int d0 = s * 16 + 2 * t4;
            const __half* ra = qbh + (size_t)(gh * 32 + d0) * HW;
            const __half* rb = qbh + (size_t)(gh * 32 + d0 + 1) * HW;
            const __half* rc = qbh + (size_t)(gh * 32 + d0 + 8) * HW;
            const __half* rd = qbh + (size_t)(gh * 32 + d0 + 9) * HW;
            int qq = qW + g;
            qa[h][s][0] = hh2pack(ra[qq],     rb[qq]);
            qa[h][s][1] = hh2pack(ra[qq + 8], rb[qq + 8]);
            qa[h][s][2] = hh2pack(rc[qq],     rd[qq]);
            qa[h][s][3] = hh2pack(rc[qq + 8], rd[qq + 8]);
        }
    }

    float oacc[4][4][4];                   // [head][d-frag][pos]
#pragma unroll
    for (int i = 0; i < 4; i++)
#pragma unroll
        for (int j = 0; j < 4; j++)
#pragma unroll
            for (int q = 0; q < 4; q++) oacc[i][j][q] = 0.f;

    const uint32_t kRow = smb + KS_OFF + ((wip * 128 + r16) * 40 + c8) * 2;
    const uint32_t vRow = smb + VS_OFF + ((wip * 128 + r2) * 40 + c2) * 2;
    char* pdA = smraw + PD_OFF + (p * 2 + wip) * 2176;        // own partials
    char* pdB = smraw + PD_OFF + (p * 2 + (wip ^ 1)) * 2176;  // partner's

    auto PREFETCH = [&](int kt2) {
        if (kt2 <= 31) {
            const int k0 = kt2 * 32;
            const int bo = (kt2 % 3) * 20480;
#pragma unroll
            for (int c = 0; c < 4; c++) {
                int idx = c * 256 + t;
                int row = idx >> 2;
                int col = (idx & 3) * 8;
                CP_ASYNC16(smb + KS_OFF + bo + row * 80 + col * 2,
                           qbh + (size_t)(256 + row) * HW + k0 + col);
                CP_ASYNC16(smb + VS_OFF + bo + row * 80 + col * 2,
                           qbh + (size_t)(512 + row) * HW + k0 + col);
            }
        }
        CP_COMMIT();
    };

    PREFETCH(0);

    for (int kt = 0; kt < 32; kt++) {
        PREFETCH(kt + 1);
        CP_WAIT1();
        __syncthreads();

        const uint32_t bo = (uint32_t)(kt % 3) * 20480;

        // ---- S + exp + in-register partial denominators (own 4 heads) ----
        uint32_t eh[4][4][2];
        float pd[16];
#pragma unroll
        for (int i = 0; i < 16; i++) pd[i] = 0.f;

#pragma unroll
        for (int h = 0; h < 4; h++) {
            float sacc[4][4];
#pragma unroll
            for (int nf = 0; nf < 4; nf++)
#pragma unroll
                for (int q = 0; q < 4; q++) sacc[nf][q] = 0.f;
#pragma unroll
            for (int np = 0; np < 2; np++)
#pragma unroll
                for (int s = 0; s < 2; s++) {
                    uint32_t bk[4];
                    ldsm_x4t(bk, kRow + bo + h * 2560 + s * 1280 + np * 32);
                    mma16816(sacc[np * 2 + 0], qa[h][s], bk + 0);
                    mma16816(sacc[np * 2 + 1], qa[h][s], bk + 2);
                }
#pragma unroll
            for (int nf = 0; nf < 4; nf++) {
                float e0, e1, e2, e3;
                exp2pairf(pk2(sacc[nf][0], sacc[nf][1]), e0, e1);
                exp2pairf(pk2(sacc[nf][2], sacc[nf][3]), e2, e3);
                pd[nf * 4 + 0] += e0;
                pd[nf * 4 + 1] += e1;
                pd[nf * 4 + 2] += e2;
                pd[nf * 4 + 3] += e3;
                eh[h][nf][0] = pack_h2(e0, e1);
                eh[h][nf][1] = pack_h2(e2, e3);
            }
        }

        // ---- store own partials, hoist head-0 V frags, then pair barrier ----
#pragma unroll
        for (int nf = 0; nf < 4; nf++) {
            *(float2*)(pdA + ((g)     * 34 + nf * 8 + 2 * t4) * 4) =
                make_float2(pd[nf * 4 + 0], pd[nf * 4 + 1]);
            *(float2*)(pdA + ((g + 8) * 34 + nf * 8 + 2 * t4) * 4) =
                make_float2(pd[nf * 4 + 2], pd[nf * 4 + 3]);
        }
        uint32_t vb0[2][2][4];             // [ks][db] V frags for head 0
#pragma unroll
        for (int ks = 0; ks < 2; ks++)
#pragma unroll
            for (int db = 0; db < 2; db++)
                ldsm_x4(vb0[ks][db], vRow + bo + db * 1280 + ks * 32);

        GROUP_BAR64(1 + p);
        float rcp[16];
#pragma unroll
        for (int nf = 0; nf < 4; nf++) {
            float2 q0 = *(float2*)(pdB + ((g)     * 34 + nf * 8 + 2 * t4) * 4);
            float2 q1 = *(float2*)(pdB + ((g + 8) * 34 + nf * 8 + 2 * t4) * 4);
            rcp[nf * 4 + 0] = frcpa(pd[nf * 4 + 0] + q0.x);
            rcp[nf * 4 + 1] = frcpa(pd[nf * 4 + 1] + q0.y);
            rcp[nf * 4 + 2] = frcpa(pd[nf * 4 + 2] + q1.x);
            rcp[nf * 4 + 3] = frcpa(pd[nf * 4 + 3] + q1.y);
        }

        // ---- O += W V (W repacked in-register; V from smem as B-frags) ----
#pragma unroll
        for (int h = 0; h < 4; h++) {
#pragma unroll
            for (int ks = 0; ks < 2; ks++) {
                uint32_t wfrag[4];
                {
                    float2 f = h2f2(eh[h][2 * ks][0]);
                    wfrag[0] = pack_h2(f.x * rcp[8 * ks + 0], f.y * rcp[8 * ks + 1]);
                }
                {
                    float2 f = h2f2(eh[h][2 * ks][1]);
                    wfrag[1] = pack_h2(f.x * rcp[8 * ks + 2], f.y * rcp[8 * ks + 3]);
                }
                {
                    float2 f = h2f2(eh[h][2 * ks + 1][0]);
                    wfrag[2] = pack_h2(f.x * rcp[8 * ks + 4], f.y * rcp[8 * ks + 5]);
                }
                {
                    float2 f = h2f2(eh[h][2 * ks + 1][1]);
                    wfrag[3] = pack_h2(f.x * rcp[8 * ks + 6], f.y * rcp[8 * ks + 7]);
                }
#pragma unroll
                for (int db = 0; db < 2; db++) {
                    uint32_t vb[4];
                    if (h == 0) {
                        vb[0] = vb0[ks][db][0]; vb[1] = vb0[ks][db][1];
                        vb[2] = vb0[ks][db][2]; vb[3] = vb0[ks][db][3];
                    } else {
                        ldsm_x4(vb, vRow + bo + h * 2560 + db * 1280 + ks * 32);
                    }
                    mma16816(oacc[h][db * 2 + 0], wfrag, vb + 0);
                    mma16816(oacc[h][db * 2 + 1], wfrag, vb + 2);
                }
            }
        }
    }

    // ---- epilogue: scrambled flat-reshape layout, fp16 ----
#pragma unroll
    for (int h = 0; h < 4; h++) {
        const int gh = wip * 4 + h;
        __half* ob = af + ((size_t)(b * 256 + gh * 32 + qt * 2 + (p >> 1))) * 1024
                     + (p & 1) * 512;
#pragma unroll
        for (int nd = 0; nd < 4; nd++) {
#pragma unroll
            for (int rh = 0; rh < 2; rh++) {
                int col = (g + 8 * rh) * 32 + nd * 8 + 2 * t4;
                *(uint32_t*)(ob + col) =
                    pack_h2(oacc[h][nd][rh * 2 + 0], oacc[h][nd][rh * 2 + 1]);
            }
        }
    }
}

// ---------------------------------------------------------------------------
extern "C" void kernel_launch(void* const* d_in, const int* in_sizes, int n_in,
                              void* d_out, int out_size)
{
    const float* x      = (const float*)d_in[0];   // [8,512,32,32]
    const float* w_qkv  = (const float*)d_in[1];   // [768,512]
    const float* b_qkv  = (const float*)d_in[2];   // [768]
    const float* w_attn = (const float*)d_in[3];   // [512,256]
    const float* b_attn = (const float*)d_in[4];   // [512]
    float* out = (float*)d_out;                    // [8,512,32,32]

    void *xh, *wqh, *wah, *qkvp, *afp;
    cudaGetSymbolAddress(&xh,   g_xh);
    cudaGetSymbolAddress(&wqh,  g_wqkvh);
    cudaGetSymbolAddress(&wah,  g_wattnh);
    cudaGetSymbolAddress(&qkvp, g_qkvh);
    cudaGetSymbolAddress(&afp,  g_afh);

    cudaFuncSetAttribute((const void*)gemm_mma<768, 512, 256, __half>,
                         cudaFuncAttributeMaxDynamicSharedMemorySize, GEMM_SMEM);
    cudaFuncSetAttribute((const void*)gemm_mma<512, 256, 0, float>,
                         cudaFuncAttributeMaxDynamicSharedMemorySize, GEMM_SMEM);
    cudaFuncSetAttribute((const void*)attn_mma,
                         cudaFuncAttributeMaxDynamicSharedMemorySize, ATTN_SMEM);

    // 0) fused fp32 -> fp16 conversion (x, w_qkv, w_attn) in one launch
    f2h_all<<<(N4_ALL + 255) / 256, 256>>>(x, w_qkv, w_attn,
                                           (__half*)xh, (__half*)wqh, (__half*)wah);

    // 1) QKV projection (all-fp16 mma; bias; q rows scaled; fp16 output)
    gemm_mma<768, 512, 256, __half><<<dim3(8, 6, BATCH), 256, GEMM_SMEM>>>(
        (const __half*)wqh, (const __half*)xh, b_qkv, (__half*)qkvp,
        0.17677669529663687f);

    // 2) fp16 fused attention, in-register head softmax (R9 structure)
    attn_mma<<<dim3(16, BATCH), 256, ATTN_SMEM>>>((const __half*)qkvp,
                                                  (__half*)afp);

    // 3) output projection (all-fp16 mma; fp32 output)
    gemm_mma<512, 256, 0, float><<<dim3(8, 4, BATCH), 256, GEMM_SMEM>>>(
        (const __half*)wah, (const __half*)afp, b_attn, out, 1.0f);
}

// round 12
// speedup vs baseline: 1.6300x; 1.1555x over previous
#include <cuda_runtime.h>
#include <cuda_fp16.h>
#include <cstdint>

#define BATCH 8
#define HW    1024
#define QKV_CH 768

// Scratch (device globals; no allocation allowed)
__device__ __half g_xh    [BATCH * 512 * HW];   // x in fp16
__device__ __half g_wqkvh [QKV_CH * 512];       // w_qkv fp16
__device__ __half g_wattnh[512 * 256];          // w_attn fp16
__device__ __half g_qkvh  [BATCH * QKV_CH * HW];
__device__ __half g_afh   [BATCH * 256 * HW];   // attention out, scrambled layout

// ===========================================================================
// helpers
// ===========================================================================
__device__ __forceinline__ uint32_t smem_u32(const void* p) {
    uint32_t a;
    asm("{ .reg .u64 t; cvta.to.shared.u64 t, %1; cvt.u32.u64 %0, t; }"
        : "=r"(a) : "l"(p));
    return a;
}
__device__ __forceinline__ void mma16816(float* c, const uint32_t* a, const uint32_t* b) {
    asm volatile("mma.sync.aligned.m16n8k16.row.col.f32.f16.f16.f32 "
        "{%0,%1,%2,%3}, {%4,%5,%6,%7}, {%8,%9}, {%0,%1,%2,%3};"
        : "+f"(c[0]), "+f"(c[1]), "+f"(c[2]), "+f"(c[3])
        : "r"(a[0]), "r"(a[1]), "r"(a[2]), "r"(a[3]), "r"(b[0]), "r"(b[1]));
}
__device__ __forceinline__ void ldsm_x4(uint32_t* r, uint32_t addr) {
    asm volatile("ldmatrix.sync.aligned.m8n8.x4.shared.b16 {%0,%1,%2,%3}, [%4];"
        : "=r"(r[0]), "=r"(r[1]), "=r"(r[2]), "=r"(r[3]) : "r"(addr));
}
__device__ __forceinline__ void ldsm_x4t(uint32_t* r, uint32_t addr) {
    asm volatile("ldmatrix.sync.aligned.m8n8.x4.trans.shared.b16 {%0,%1,%2,%3}, [%4];"
        : "=r"(r[0]), "=r"(r[1]), "=r"(r[2]), "=r"(r[3]) : "r"(addr));
}
__device__ __forceinline__ uint32_t pack_h2(float lo, float hi) {
    __half2 h = __floats2half2_rn(lo, hi);
    return *reinterpret_cast<uint32_t*>(&h);
}
__device__ __forceinline__ uint32_t hh2pack(__half a, __half b) {
    __half2 h = __halves2half2(a, b);
    return *reinterpret_cast<uint32_t*>(&h);
}
__device__ __forceinline__ uint32_t hmul2(uint32_t a, uint32_t b) {
    uint32_t d;
    asm("mul.rn.f16x2 %0, %1, %2;" : "=r"(d) : "r"(a), "r"(b));
    return d;
}
// MUFU exp2 / reciprocal
__device__ __forceinline__ float ex2f(float y) {
    float r; asm("ex2.approx.f32 %0, %1;" : "=f"(r) : "f"(y)); return r;
}
__device__ __forceinline__ float frcpa(float x) {
    float r; asm("rcp.approx.f32 %0, %1;" : "=f"(r) : "f"(x)); return r;
}
#define CP_ASYNC16(dst, src) \
    asm volatile("cp.async.cg.shared.global [%0], [%1], 16;" \
                 :: "r"(dst), "l"(src) : "memory")
#define CP_COMMIT() asm volatile("cp.async.commit_group;" ::: "memory")
#define CP_WAIT1()  asm volatile("cp.async.wait_group 1;" ::: "memory")
#define GROUP_BAR64(id) asm volatile("bar.sync %0, 64;" :: "r"(id) : "memory")

#define LOG2E 1.4426950408889634f

// ===========================================================================
// fused fp32 -> fp16 conversion for x, w_qkv, w_attn (one launch)
// ===========================================================================
static constexpr int N4_X  = 1048576;
static constexpr int N4_WQ = 98304;
static constexpr int N4_WA = 32768;
static constexpr int N4_ALL = N4_X + N4_WQ + N4_WA;

__global__ void f2h_all(const float* __restrict__ x, const float* __restrict__ wq,
                        const float* __restrict__ wa,
                        __half* __restrict__ xh, __half* __restrict__ wqh,
                        __half* __restrict__ wah)
{
    int i = blockIdx.x * blockDim.x + threadIdx.x;
    const float* src;
    __half* dst;
    int j;
    if (i < N4_X)                 { src = x;  dst = xh;  j = i; }
    else if (i < N4_X + N4_WQ)    { src = wq; dst = wqh; j = i - N4_X; }
    else if (i < N4_ALL)          { src = wa; dst = wah; j = i - N4_X - N4_WQ; }
    else return;
    float4 v = ((const float4*)src)[j];
    uint2 p;
    p.x = pack_h2(v.x, v.y);
    p.y = pack_h2(v.z, v.w);
    ((uint2*)dst)[j] = p;
}

// ===========================================================================
// all-fp16 mma.sync GEMM, cp.async 3-stage, 2 CTAs/SM
// ===========================================================================
static constexpr int GASZ = 128 * 80;
static constexpr int GBSZ = 32 * 272;
static constexpr int GSTG = GASZ + GBSZ;
static constexpr int GEMM_SMEM = 3 * GSTG;

template<int M, int K, int SCALE_ROWS, typename TY>
__global__ __launch_bounds__(256, 2)
void gemm_mma(const __half* __restrict__ W, const __half* __restrict__ X,
              const float* __restrict__ bias, TY* __restrict__ Y,
              float scaleVal)
{
    extern __shared__ char smraw[];
    const uint32_t smb = smem_u32(smraw);

    const int t    = threadIdx.x;
    const int lane = t & 31;
    const int wid  = t >> 5;
    const int g    = lane >> 2;
    const int t4   = lane & 3;
    const int wm   = (wid & 1) * 64;
    const int wn   = (wid >> 1) * 32;
    const int b    = blockIdx.z;
    const int m0   = blockIdx.y * 128;
    const int n0   = blockIdx.x * 128;
    const __half* Xb = X + (size_t)b * K * 1024;
    TY*           Yb = Y + (size_t)b * M * 1024;

    const int r16 = lane & 15;
    const int c8  = (lane >> 4) * 8;
    const uint32_t aAddr = smb + (wm + r16) * 80 + c8 * 2;
    const uint32_t bAddr = smb + GASZ + r16 * 272 + (wn + c8) * 2;

    const int NC = K / 32;
    auto PRE = [&](int kc) {
        if (kc < NC) {
            const uint32_t so = (uint32_t)(kc % 3) * GSTG;
#pragma unroll
            for (int c = 0; c < 2; c++) {
                int ch = c * 256 + t;
                int ar = ch >> 2, ac = (ch & 3) * 8;
                CP_ASYNC16(smb + so + ar * 80 + ac * 2,
                           W + (size_t)(m0 + ar) * K + kc * 32 + ac);
                int br = ch >> 4, bc = (ch & 15) * 8;
                CP_ASYNC16(smb + so + GASZ + br * 272 + bc * 2,
                           Xb + (size_t)(kc * 32 + br) * 1024 + n0 + bc);
            }
        }
        CP_COMMIT();
    };

    float acc[4][4][4];
#pragma unroll
    for (int i = 0; i < 4; i++)
#pragma unroll
        for (int j = 0; j < 4; j++)
#pragma unroll
            for (int q = 0; q < 4; q++) acc[i][j][q] = 0.f;

    PRE(0);
    PRE(1);

    for (int kc = 0; kc < NC; kc++) {
        CP_WAIT1();
        __syncthreads();
        PRE(kc + 2);

        const uint32_t so = (uint32_t)(kc % 3) * GSTG;
        const uint32_t aB = aAddr + so;
        const uint32_t bB = bAddr + so;
#pragma unroll
        for (int s = 0; s < 2; s++) {
            uint32_t afr[4][4], bfr[2][4];
#pragma unroll
            for (int mf = 0; mf < 4; mf++)
                ldsm_x4(afr[mf], aB + mf * 16 * 80 + s * 32);
#pragma unroll
            for (int np = 0; np < 2; np++)
                ldsm_x4t(bfr[np], bB + np * 32 + s * 16 * 272);
#pragma unroll
            for (int mf = 0; mf < 4; mf++)
#pragma unroll
                for (int np = 0; np < 2; np++) {
                    mma16816(acc[mf][2 * np],     afr[mf], bfr[np] + 0);
                    mma16816(acc[mf][2 * np + 1], afr[mf], bfr[np] + 2);
                }
        }
    }

#pragma unroll
    for (int mf = 0; mf < 4; mf++) {
        int r0 = m0 + wm + mf * 16 + g;
        int r1 = r0 + 8;
        float b0v = bias[r0], b1v = bias[r1];
        float s0 = (SCALE_ROWS > 0 && r0 < SCALE_ROWS) ? scaleVal : 1.f;
        float s1 = (SCALE_ROWS > 0 && r1 < SCALE_ROWS) ? scaleVal : 1.f;
#pragma unroll
        for (int nf = 0; nf < 4; nf++) {
            int nc = n0 + wn + nf * 8 + 2 * t4;
            if constexpr (sizeof(TY) == 2) {
                *(uint32_t*)&Yb[(size_t)r0 * 1024 + nc] =
                    pack_h2((acc[mf][nf][0] + b0v) * s0, (acc[mf][nf][1] + b0v) * s0);
                *(uint32_t*)&Yb[(size_t)r1 * 1024 + nc] =
                    pack_h2((acc[mf][nf][2] + b1v) * s1, (acc[mf][nf][3] + b1v) * s1);
            } else {
                float2 v0, v1;
                v0.x = (acc[mf][nf][0] + b0v) * s0;
                v0.y = (acc[mf][nf][1] + b0v) * s0;
                v1.x = (acc[mf][nf][2] + b1v) * s1;
                v1.y = (acc[mf][nf][3] + b1v) * s1;
                *(float2*)&Yb[(size_t)r0 * 1024 + nc] = v0;
                *(float2*)&Yb[(size_t)r1 * 1024 + nc] = v1;
            }
        }
    }
}

// ===========================================================================
// fp16 fused attention, in-register head softmax (R9/R11 structure).
// Softmax arithmetic moved off the FMA pipe: exp via MUFU ex2.approx.f32,
// W-repack via mul.rn.f16x2 (one HMUL2 per A-frag word, rcp pre-packed to
// half2). Softmax across the 8 HEADS. Output: scrambled reshape, fp16.
// ===========================================================================
static constexpr int KS_OFF = 0;                    // 3 x 20480
static constexpr int VS_OFF = 3 * 20480;            // 3 x 20480
static constexpr int PD_OFF = 6 * 20480;            // 8 x 2176
static constexpr int ATTN_SMEM = PD_OFF + 8 * 2176; // 140288 B

__global__ __launch_bounds__(256, 1)
void attn_mma(const __half* __restrict__ qkvh, __half* __restrict__ af)
{
    extern __shared__ char smraw[];
    const uint32_t smb = smem_u32(smraw);

    const int b    = blockIdx.y;
    const int qt   = blockIdx.x;           // 16 tiles of 64 queries
    const int t    = threadIdx.x;
    const int lane = t & 31;
    const int w    = t >> 5;               // 8 warps
    const int p    = w >> 1;               // pair 0..3
    const int wip  = w & 1;                // 0: heads 0-3, 1: heads 4-7
    const int g    = lane >> 2;
    const int t4   = lane & 3;

    const int r16 = lane & 15;
    const int c8  = (lane >> 4) * 8;
    const int r2  = (lane & 7) + (lane >> 4) * 8;
    const int c2  = ((lane >> 3) & 1) * 8;

    const int qW = qt * 64 + p * 16;       // this pair's 16-query slice
    const __half* qbh = qkvh + (size_t)b * QKV_CH * HW;

    // ---- preload Q A-fragments for 4 heads (reused all 32 tiles) ----
    uint32_t qa[4][2][4];
#pragma unroll
    for (int h = 0; h < 4; h++) {
        const int gh = wip * 4 + h;
#pragma unroll
        for (int s = 0; s < 2; s++) {
            int d0 = s * 16 + 2 * t4;
            const __half* ra = qbh + (size_t)(gh * 32 + d0) * HW;
            const __half* rb = qbh + (size_t)(gh * 32 + d0 + 1) * HW;
            const __half* rc = qbh + (size_t)(gh * 32 + d0 + 8) * HW;
            const __half* rd = qbh + (size_t)(gh * 32 + d0 + 9) * HW;
            int qq = qW + g;
            qa[h][s][0] = hh2pack(ra[qq],     rb[qq]);
            qa[h][s][1] = hh2pack(ra[qq + 8], rb[qq + 8]);
            qa[h][s][2] = hh2pack(rc[qq],     rd[qq]);
            qa[h][s][3] = hh2pack(rc[qq + 8], rd[qq + 8]);
        }
    }

    float oacc[4][4][4];                   // [head][d-frag][pos]
#pragma unroll
    for (int i = 0; i < 4; i++)
#pragma unroll
        for (int j = 0; j < 4; j++)
#pragma unroll
            for (int q = 0; q < 4; q++) oacc[i][j][q] = 0.f;

    const uint32_t kRow = smb + KS_OFF + ((wip * 128 + r16) * 40 + c8) * 2;
    const uint32_t vRow = smb + VS_OFF + ((wip * 128 + r2) * 40 + c2) * 2;
    char* pdA = smraw + PD_OFF + (p * 2 + wip) * 2176;        // own partials
    char* pdB = smraw + PD_OFF + (p * 2 + (wip ^ 1)) * 2176;  // partner's

    auto PREFETCH = [&](int kt2) {
        if (kt2 <= 31) {
            const int k0 = kt2 * 32;
            const int bo = (kt2 % 3) * 20480;
#pragma unroll
            for (int c = 0; c < 4; c++) {
                int idx = c * 256 + t;
                int row = idx >> 2;
                int col = (idx & 3) * 8;
                CP_ASYNC16(smb + KS_OFF + bo + row * 80 + col * 2,
                           qbh + (size_t)(256 + row) * HW + k0 + col);
                CP_ASYNC16(smb + VS_OFF + bo + row * 80 + col * 2,
                           qbh + (size_t)(512 + row) * HW + k0 + col);
            }
        }
        CP_COMMIT();
    };

    PREFETCH(0);

    for (int kt = 0; kt < 32; kt++) {
        PREFETCH(kt + 1);
        CP_WAIT1();
        __syncthreads();

        const uint32_t bo = (uint32_t)(kt % 3) * 20480;

        // ---- S + MUFU exp + in-register partial denominators (4 heads) ----
        uint32_t eh[4][4][2];
        float pd[16];
#pragma unroll
        for (int i = 0; i < 16; i++) pd[i] = 0.f;

#pragma unroll
        for (int h = 0; h < 4; h++) {
            float sacc[4][4];
#pragma unroll
            for (int nf = 0; nf < 4; nf++)
#pragma unroll
                for (int q = 0; q < 4; q++) sacc[nf][q] = 0.f;
#pragma unroll
            for (int np = 0; np < 2; np++)
#pragma unroll
                for (int s = 0; s < 2; s++) {
                    uint32_t bk[4];
                    ldsm_x4t(bk, kRow + bo + h * 2560 + s * 1280 + np * 32);
                    mma16816(sacc[np * 2 + 0], qa[h][s], bk + 0);
                    mma16816(sacc[np * 2 + 1], qa[h][s], bk + 2);
                }
#pragma unroll
            for (int nf = 0; nf < 4; nf++) {
                float e0 = ex2f(sacc[nf][0] * LOG2E);
                float e1 = ex2f(sacc[nf][1] * LOG2E);
                float e2 = ex2f(sacc[nf][2] * LOG2E);
                float e3 = ex2f(sacc[nf][3] * LOG2E);
                pd[nf * 4 + 0] += e0;
                pd[nf * 4 + 1] += e1;
                pd[nf * 4 + 2] += e2;
                pd[nf * 4 + 3] += e3;
                eh[h][nf][0] = pack_h2(e0, e1);
                eh[h][nf][1] = pack_h2(e2, e3);
            }
        }

        // ---- store own partials, hoist head-0 V frags, then pair barrier ----
#pragma unroll
        for (int nf = 0; nf < 4; nf++) {
            *(float2*)(pdA + ((g)     * 34 + nf * 8 + 2 * t4) * 4) =
                make_float2(pd[nf * 4 + 0], pd[nf * 4 + 1]);
            *(float2*)(pdA + ((g + 8) * 34 + nf * 8 + 2 * t4) * 4) =
                make_float2(pd[nf * 4 + 2], pd[nf * 4 + 3]);
        }
        uint32_t vb0[2][2][4];             // [ks][db] V frags for head 0
#pragma unroll
        for (int ks = 0; ks < 2; ks++)
#pragma unroll
            for (int db = 0; db < 2; db++)
                ldsm_x4(vb0[ks][db], vRow + bo + db * 1280 + ks * 32);

        GROUP_BAR64(1 + p);

        // ---- full denominators -> rcp (MUFU) -> pre-packed half2 ----
        uint32_t rcph[4][2];
#pragma unroll
        for (int nf = 0; nf < 4; nf++) {
            float2 q0 = *(float2*)(pdB + ((g)     * 34 + nf * 8 + 2 * t4) * 4);
            float2 q1 = *(float2*)(pdB + ((g + 8) * 34 + nf * 8 + 2 * t4) * 4);
            float r0 = frcpa(pd[nf * 4 + 0] + q0.x);
            float r1 = frcpa(pd[nf * 4 + 1] + q0.y);
            float r2 = frcpa(pd[nf * 4 + 2] + q1.x);
            float r3 = frcpa(pd[nf * 4 + 3] + q1.y);
            rcph[nf][0] = pack_h2(r0, r1);
            rcph[nf][1] = pack_h2(r2, r3);
        }

        // ---- O += W V (W = eh * rcph via HMUL2; V from smem as B-frags) ----
#pragma unroll
        for (int h = 0; h < 4; h++) {
#pragma unroll
            for (int ks = 0; ks < 2; ks++) {
                uint32_t wfrag[4];
                wfrag[0] = hmul2(eh[h][2 * ks][0],     rcph[2 * ks][0]);
                wfrag[1] = hmul2(eh[h][2 * ks][1],     rcph[2 * ks][1]);
                wfrag[2] = hmul2(eh[h][2 * ks + 1][0], rcph[2 * ks + 1][0]);
                wfrag[3] = hmul2(eh[h][2 * ks + 1][1], rcph[2 * ks + 1][1]);
#pragma unroll
                for (int db = 0; db < 2; db++) {
                    uint32_t vb[4];
                    if (h == 0) {
                        vb[0] = vb0[ks][db][0]; vb[1] = vb0[ks][db][1];
                        vb[2] = vb0[ks][db][2]; vb[3] = vb0[ks][db][3];
                    } else {
                        ldsm_x4(vb, vRow + bo + h * 2560 + db * 1280 + ks * 32);
                    }
                    mma16816(oacc[h][db * 2 + 0], wfrag, vb + 0);
                    mma16816(oacc[h][db * 2 + 1], wfrag, vb + 2);
                }
            }
        }
    }

    // ---- epilogue: scrambled flat-reshape layout, fp16 ----
#pragma unroll
    for (int h = 0; h < 4; h++) {
        const int gh = wip * 4 + h;
        __half* ob = af + ((size_t)(b * 256 + gh * 32 + qt * 2 + (p >> 1))) * 1024
                     + (p & 1) * 512;
#pragma unroll
        for (int nd = 0; nd < 4; nd++) {
#pragma unroll
            for (int rh = 0; rh < 2; rh++) {
                int col = (g + 8 * rh) * 32 + nd * 8 + 2 * t4;
                *(uint32_t*)(ob + col) =
                    pack_h2(oacc[h][nd][rh * 2 + 0], oacc[h][nd][rh * 2 + 1]);
            }
        }
    }
}

// ---------------------------------------------------------------------------
extern "C" void kernel_launch(void* const* d_in, const int* in_sizes, int n_in,
                              void* d_out, int out_size)
{
    const float* x      = (const float*)d_in[0];   // [8,512,32,32]
    const float* w_qkv  = (const float*)d_in[1];   // [768,512]
    const float* b_qkv  = (const float*)d_in[2];   // [768]
    const float* w_attn = (const float*)d_in[3];   // [512,256]
    const float* b_attn = (const float*)d_in[4];   // [512]
    float* out = (float*)d_out;                    // [8,512,32,32]

    void *xh, *wqh, *wah, *qkvp, *afp;
    cudaGetSymbolAddress(&xh,   g_xh);
    cudaGetSymbolAddress(&wqh,  g_wqkvh);
    cudaGetSymbolAddress(&wah,  g_wattnh);
    cudaGetSymbolAddress(&qkvp, g_qkvh);
    cudaGetSymbolAddress(&afp,  g_afh);

    cudaFuncSetAttribute((const void*)gemm_mma<768, 512, 256, __half>,
                         cudaFuncAttributeMaxDynamicSharedMemorySize, GEMM_SMEM);
    cudaFuncSetAttribute((const void*)gemm_mma<512, 256, 0, float>,
                         cudaFuncAttributeMaxDynamicSharedMemorySize, GEMM_SMEM);
    cudaFuncSetAttribute((const void*)attn_mma,
                         cudaFuncAttributeMaxDynamicSharedMemorySize, ATTN_SMEM);

    // 0) fused fp32 -> fp16 conversion (x, w_qkv, w_attn)
    f2h_all<<<(N4_ALL + 255) / 256, 256>>>(x, w_qkv, w_attn,
                                           (__half*)xh, (__half*)wqh, (__half*)wah);

    // 1) QKV projection (all-fp16 mma; bias; q rows scaled; fp16 output)
    gemm_mma<768, 512, 256, __half><<<dim3(8, 6, BATCH), 256, GEMM_SMEM>>>(
        (const __half*)wqh, (const __half*)xh, b_qkv, (__half*)qkvp,
        0.17677669529663687f);

    // 2) fp16 fused attention, MUFU softmax
    attn_mma<<<dim3(16, BATCH), 256, ATTN_SMEM>>>((const __half*)qkvp,
                                                  (__half*)afp);

    // 3) output projection (all-fp16 mma; fp32 output)
    gemm_mma<512, 256, 0, float><<<dim3(8, 4, BATCH), 256, GEMM_SMEM>>>(
        (const __half*)wah, (const __half*)afp, b_attn, out, 1.0f);
}

// round 14
// speedup vs baseline: 1.9241x; 1.1804x over previous
#include <cuda_runtime.h>
#include <cuda_fp16.h>
#include <cstdint>

#define BATCH 8
#define HW    1024
#define QKV_CH 768

// Scratch (device globals; no allocation allowed)
__device__ __half g_xh    [BATCH * 512 * HW];   // x in fp16
__device__ __half g_wqkvh [QKV_CH * 512];       // w_qkv fp16
__device__ __half g_wattnh[512 * 256];          // w_attn fp16
__device__ __half g_qkvh  [BATCH * QKV_CH * HW];
__device__ __half g_afh   [BATCH * 256 * HW];   // attention out, scrambled layout

// ===========================================================================
// helpers
// ===========================================================================
__device__ __forceinline__ uint32_t smem_u32(const void* p) {
    uint32_t a;
    asm("{ .reg .u64 t; cvta.to.shared.u64 t, %1; cvt.u32.u64 %0, t; }"
        : "=r"(a) : "l"(p));
    return a;
}
__device__ __forceinline__ void mma16816(float* c, const uint32_t* a, const uint32_t* b) {
    asm volatile("mma.sync.aligned.m16n8k16.row.col.f32.f16.f16.f32 "
        "{%0,%1,%2,%3}, {%4,%5,%6,%7}, {%8,%9}, {%0,%1,%2,%3};"
        : "+f"(c[0]), "+f"(c[1]), "+f"(c[2]), "+f"(c[3])
        : "r"(a[0]), "r"(a[1]), "r"(a[2]), "r"(a[3]), "r"(b[0]), "r"(b[1]));
}
__device__ __forceinline__ void ldsm_x4(uint32_t* r, uint32_t addr) {
    asm volatile("ldmatrix.sync.aligned.m8n8.x4.shared.b16 {%0,%1,%2,%3}, [%4];"
        : "=r"(r[0]), "=r"(r[1]), "=r"(r[2]), "=r"(r[3]) : "r"(addr));
}
__device__ __forceinline__ void ldsm_x4t(uint32_t* r, uint32_t addr) {
    asm volatile("ldmatrix.sync.aligned.m8n8.x4.trans.shared.b16 {%0,%1,%2,%3}, [%4];"
        : "=r"(r[0]), "=r"(r[1]), "=r"(r[2]), "=r"(r[3]) : "r"(addr));
}
__device__ __forceinline__ uint32_t pack_h2(float lo, float hi) {
    __half2 h = __floats2half2_rn(lo, hi);
    return *reinterpret_cast<uint32_t*>(&h);
}
__device__ __forceinline__ uint32_t hh2pack(__half a, __half b) {
    __half2 h = __halves2half2(a, b);
    return *reinterpret_cast<uint32_t*>(&h);
}
__device__ __forceinline__ float2 h2f2(uint32_t u) {
    __half2 h = *reinterpret_cast<__half2*>(&u);
    return __half22float2(h);
}
__device__ __forceinline__ uint32_t hmul2(uint32_t a, uint32_t b) {
    uint32_t d;
    asm("mul.rn.f16x2 %0, %1, %2;" : "=r"(d) : "r"(a), "r"(b));
    return d;
}
__device__ __forceinline__ uint32_t hadd2(uint32_t a, uint32_t b) {
    uint32_t d;
    asm("add.rn.f16x2 %0, %1, %2;" : "=r"(d) : "r"(a), "r"(b));
    return d;
}
// MUFU packed fp16 exp2 (valid at sm_103 generic)
__device__ __forceinline__ uint32_t hex2(uint32_t a) {
    uint32_t d;
    asm("ex2.approx.f16x2 %0, %1;" : "=r"(d) : "r"(a));
    return d;
}
__device__ __forceinline__ float frcpa(float x) {
    float r; asm("rcp.approx.f32 %0, %1;" : "=f"(r) : "f"(x)); return r;
}
// packed reciprocal via 2x f32 MUFU rcp (f16x2 rcp not supported at sm_103)
__device__ __forceinline__ uint32_t hrcp2(uint32_t a) {
    float2 f = h2f2(a);
    return pack_h2(frcpa(f.x), frcpa(f.y));
}
#define CP_ASYNC16(dst, src) \
    asm volatile("cp.async.cg.shared.global [%0], [%1], 16;" \
                 :: "r"(dst), "l"(src) : "memory")
#define CP_COMMIT() asm volatile("cp.async.commit_group;" ::: "memory")
#define CP_WAIT1()  asm volatile("cp.async.wait_group 1;" ::: "memory")
#define GROUP_BAR64(id) asm volatile("bar.sync %0, 64;" :: "r"(id) : "memory")

// ===========================================================================
// fused fp32 -> fp16 conversion for x, w_qkv, w_attn (one launch)
// ===========================================================================
static constexpr int N4_X  = 1048576;
static constexpr int N4_WQ = 98304;
static constexpr int N4_WA = 32768;
static constexpr int N4_ALL = N4_X + N4_WQ + N4_WA;

__global__ void f2h_all(const float* __restrict__ x, const float* __restrict__ wq,
                        const float* __restrict__ wa,
                        __half* __restrict__ xh, __half* __restrict__ wqh,
                        __half* __restrict__ wah)
{
    int i = blockIdx.x * blockDim.x + threadIdx.x;
    const float* src;
    __half* dst;
    int j;
    if (i < N4_X)                 { src = x;  dst = xh;  j = i; }
    else if (i < N4_X + N4_WQ)    { src = wq; dst = wqh; j = i - N4_X; }
    else if (i < N4_ALL)          { src = wa; dst = wah; j = i - N4_X - N4_WQ; }
    else return;
    float4 v = ((const float4*)src)[j];
    uint2 p;
    p.x = pack_h2(v.x, v.y);
    p.y = pack_h2(v.z, v.w);
    ((uint2*)dst)[j] = p;
}

// ===========================================================================
// all-fp16 mma.sync GEMM, cp.async 3-stage, 2 CTAs/SM
// ===========================================================================
static constexpr int GASZ = 128 * 80;
static constexpr int GBSZ = 32 * 272;
static constexpr int GSTG = GASZ + GBSZ;
static constexpr int GEMM_SMEM = 3 * GSTG;

template<int M, int K, int SCALE_ROWS, typename TY>
__global__ __launch_bounds__(256, 2)
void gemm_mma(const __half* __restrict__ W, const __half* __restrict__ X,
              const float* __restrict__ bias, TY* __restrict__ Y,
              float scaleVal)
{
    extern __shared__ char smraw[];
    const uint32_t smb = smem_u32(smraw);

    const int t    = threadIdx.x;
    const int lane = t & 31;
    const int wid  = t >> 5;
    const int g    = lane >> 2;
    const int t4   = lane & 3;
    const int wm   = (wid & 1) * 64;
    const int wn   = (wid >> 1) * 32;
    const int b    = blockIdx.z;
    const int m0   = blockIdx.y * 128;
    const int n0   = blockIdx.x * 128;
    const __half* Xb = X + (size_t)b * K * 1024;
    TY*           Yb = Y + (size_t)b * M * 1024;

    const int r16 = lane & 15;
    const int c8  = (lane >> 4) * 8;
    const uint32_t aAddr = smb + (wm + r16) * 80 + c8 * 2;
    const uint32_t bAddr = smb + GASZ + r16 * 272 + (wn + c8) * 2;

    const int NC = K / 32;
    auto PRE = [&](int kc) {
        if (kc < NC) {
            const uint32_t so = (uint32_t)(kc % 3) * GSTG;
#pragma unroll
            for (int c = 0; c < 2; c++) {
                int ch = c * 256 + t;
                int ar = ch >> 2, ac = (ch & 3) * 8;
                CP_ASYNC16(smb + so + ar * 80 + ac * 2,
                           W + (size_t)(m0 + ar) * K + kc * 32 + ac);
                int br = ch >> 4, bc = (ch & 15) * 8;
                CP_ASYNC16(smb + so + GASZ + br * 272 + bc * 2,
                           Xb + (size_t)(kc * 32 + br) * 1024 + n0 + bc);
            }
        }
        CP_COMMIT();
    };

    float acc[4][4][4];
#pragma unroll
    for (int i = 0; i < 4; i++)
#pragma unroll
        for (int j = 0; j < 4; j++)
#pragma unroll
            for (int q = 0; q < 4; q++) acc[i][j][q] = 0.f;

    PRE(0);
    PRE(1);

    for (int kc = 0; kc < NC; kc++) {
        CP_WAIT1();
        __syncthreads();
        PRE(kc + 2);

        const uint32_t so = (uint32_t)(kc % 3) * GSTG;
        const uint32_t aB = aAddr + so;
        const uint32_t bB = bAddr + so;
#pragma unroll
        for (int s = 0; s < 2; s++) {
            uint32_t afr[4][4], bfr[2][4];
#pragma unroll
            for (int mf = 0; mf < 4; mf++)
                ldsm_x4(afr[mf], aB + mf * 16 * 80 + s * 32);
#pragma unroll
            for (int np = 0; np < 2; np++)
                ldsm_x4t(bfr[np], bB + np * 32 + s * 16 * 272);
#pragma unroll
            for (int mf = 0; mf < 4; mf++)
#pragma unroll
                for (int np = 0; np < 2; np++) {
                    mma16816(acc[mf][2 * np],     afr[mf], bfr[np] + 0);
                    mma16816(acc[mf][2 * np + 1], afr[mf], bfr[np] + 2);
                }
        }
    }

#pragma unroll
    for (int mf = 0; mf < 4; mf++) {
        int r0 = m0 + wm + mf * 16 + g;
        int r1 = r0 + 8;
        float b0v = bias[r0], b1v = bias[r1];
        float s0 = (SCALE_ROWS > 0 && r0 < SCALE_ROWS) ? scaleVal : 1.f;
        float s1 = (SCALE_ROWS > 0 && r1 < SCALE_ROWS) ? scaleVal : 1.f;
#pragma unroll
        for (int nf = 0; nf < 4; nf++) {
            int nc = n0 + wn + nf * 8 + 2 * t4;
            if constexpr (sizeof(TY) == 2) {
                *(uint32_t*)&Yb[(size_t)r0 * 1024 + nc] =
                    pack_h2((acc[mf][nf][0] + b0v) * s0, (acc[mf][nf][1] + b0v) * s0);
                *(uint32_t*)&Yb[(size_t)r1 * 1024 + nc] =
                    pack_h2((acc[mf][nf][2] + b1v) * s1, (acc[mf][nf][3] + b1v) * s1);
            } else {
                float2 v0, v1;
                v0.x = (acc[mf][nf][0] + b0v) * s0;
                v0.y = (acc[mf][nf][1] + b0v) * s0;
                v1.x = (acc[mf][nf][2] + b1v) * s1;
                v1.y = (acc[mf][nf][3] + b1v) * s1;
                *(float2*)&Yb[(size_t)r0 * 1024 + nc] = v0;
                *(float2*)&Yb[(size_t)r1 * 1024 + nc] = v1;
            }
        }
    }
}

// ===========================================================================
// fp16 fused attention, in-register head softmax, packed-fp16 MUFU softmax:
// q arrives pre-scaled by dkh^-0.5 * log2(e) (folded into QKV epilogue), so
// exp = ex2.approx.f16x2 directly on the packed S fragment. Denominators
// accumulated in half2 (HADD2), pair-exchanged, reciprocal via 2x
// rcp.approx.f32 (f16x2 rcp unsupported at sm_103) repacked to half2 for the
// HMUL2 W-repack. Softmax across the 8 HEADS. Output: scrambled reshape.
// ===========================================================================
static constexpr int KS_OFF = 0;                    // 3 x 20480
static constexpr int VS_OFF = 3 * 20480;            // 3 x 20480
static constexpr int PD_OFF = 6 * 20480;            // 8 x 2176
static constexpr int ATTN_SMEM = PD_OFF + 8 * 2176; // 140288 B

__global__ __launch_bounds__(256, 1)
void attn_mma(const __half* __restrict__ qkvh, __half* __restrict__ af)
{
    extern __shared__ char smraw[];
    const uint32_t smb = smem_u32(smraw);

    const int b    = blockIdx.y;
    const int qt   = blockIdx.x;           // 16 tiles of 64 queries
    const int t    = threadIdx.x;
    const int lane = t & 31;
    const int w    = t >> 5;               // 8 warps
    const int p    = w >> 1;               // pair 0..3
    const int wip  = w & 1;                // 0: heads 0-3, 1: heads 4-7
    const int g    = lane >> 2;
    const int t4   = lane & 3;

    const int r16 = lane & 15;
    const int c8  = (lane >> 4) * 8;
    const int r2  = (lane & 7) + (lane >> 4) * 8;
    const int c2  = ((lane >> 3) & 1) * 8;

    const int qW = qt * 64 + p * 16;       // this pair's 16-query slice
    const __half* qbh = qkvh + (size_t)b * QKV_CH * HW;

    // ---- preload Q A-fragments for 4 heads (reused all 32 tiles) ----
    uint32_t qa[4][2][4];
#pragma unroll
    for (int h = 0; h < 4; h++) {
        const int gh = wip * 4 + h;
#pragma unroll
        for (int s = 0; s < 2; s++) {
            int d0 = s * 16 + 2 * t4;
            const __half* ra = qbh + (size_t)(gh * 32 + d0) * HW;
            const __half* rb = qbh + (size_t)(gh * 32 + d0 + 1) * HW;
            const __half* rc = qbh + (size_t)(gh * 32 + d0 + 8) * HW;
            const __half* rd = qbh + (size_t)(gh * 32 + d0 + 9) * HW;
            int qq = qW + g;
            qa[h][s][0] = hh2pack(ra[qq],     rb[qq]);
            qa[h][s][1] = hh2pack(ra[qq + 8], rb[qq + 8]);
            qa[h][s][2] = hh2pack(rc[qq],     rd[qq]);
            qa[h][s][3] = hh2pack(rc[qq + 8], rd[qq + 8]);
        }
    }

    float oacc[4][4][4];                   // [head][d-frag][pos]
#pragma unroll
    for (int i = 0; i < 4; i++)
#pragma unroll
        for (int j = 0; j < 4; j++)
#pragma unroll
            for (int q = 0; q < 4; q++) oacc[i][j][q] = 0.f;

    const uint32_t kRow = smb + KS_OFF + ((wip * 128 + r16) * 40 + c8) * 2;
    const uint32_t vRow = smb + VS_OFF + ((wip * 128 + r2) * 40 + c2) * 2;
    char* pdA = smraw + PD_OFF + (p * 2 + wip) * 2176;        // own partials
    char* pdB = smraw + PD_OFF + (p * 2 + (wip ^ 1)) * 2176;  // partner's

    auto PREFETCH = [&](int kt2) {
        if (kt2 <= 31) {
            const int k0 = kt2 * 32;
            const int bo = (kt2 % 3) * 20480;
#pragma unroll
            for (int c = 0; c < 4; c++) {
                int idx = c * 256 + t;
                int row = idx >> 2;
                int col = (idx & 3) * 8;
                CP_ASYNC16(smb + KS_OFF + bo + row * 80 + col * 2,
                           qbh + (size_t)(256 + row) * HW + k0 + col);
                CP_ASYNC16(smb + VS_OFF + bo + row * 80 + col * 2,
                           qbh + (size_t)(512 + row) * HW + k0 + col);
            }
        }
        CP_COMMIT();
    };

    PREFETCH(0);

    for (int kt = 0; kt < 32; kt++) {
        PREFETCH(kt + 1);
        CP_WAIT1();
        __syncthreads();

        const uint32_t bo = (uint32_t)(kt % 3) * 20480;

        // ---- S + packed-fp16 MUFU exp + HADD2 partial denominators ----
        uint32_t eh[4][4][2];
        uint32_t pd2[4][2];                // half2 partial denoms [nf][rh]
#pragma unroll
        for (int nf = 0; nf < 4; nf++) {
            pd2[nf][0] = 0u;
            pd2[nf][1] = 0u;
        }

#pragma unroll
        for (int h = 0; h < 4; h++) {
            float sacc[4][4];
#pragma unroll
            for (int nf = 0; nf < 4; nf++)
#pragma unroll
                for (int q = 0; q < 4; q++) sacc[nf][q] = 0.f;
#pragma unroll
            for (int np = 0; np < 2; np++)
#pragma unroll
                for (int s = 0; s < 2; s++) {
                    uint32_t bk[4];
                    ldsm_x4t(bk, kRow + bo + h * 2560 + s * 1280 + np * 32);
                    mma16816(sacc[np * 2 + 0], qa[h][s], bk + 0);
                    mma16816(sacc[np * 2 + 1], qa[h][s], bk + 2);
                }
#pragma unroll
            for (int nf = 0; nf < 4; nf++) {
                uint32_t e0 = hex2(pack_h2(sacc[nf][0], sacc[nf][1]));
                uint32_t e1 = hex2(pack_h2(sacc[nf][2], sacc[nf][3]));
                eh[h][nf][0] = e0;
                eh[h][nf][1] = e1;
                pd2[nf][0] = hadd2(pd2[nf][0], e0);
                pd2[nf][1] = hadd2(pd2[nf][1], e1);
            }
        }

        // ---- store own partials, hoist heads 0-1 V frags, pair barrier ----
#pragma unroll
        for (int nf = 0; nf < 4; nf++) {
            *(uint32_t*)(pdA + (g)     * 80 + (nf * 8 + 2 * t4) * 2) = pd2[nf][0];
            *(uint32_t*)(pdA + (g + 8) * 80 + (nf * 8 + 2 * t4) * 2) = pd2[nf][1];
        }
        uint32_t vb01[2][2][2][4];         // [h][ks][db] V frags heads 0,1
#pragma unroll
        for (int h = 0; h < 2; h++)
#pragma unroll
            for (int ks = 0; ks < 2; ks++)
#pragma unroll
                for (int db = 0; db < 2; db++)
                    ldsm_x4(vb01[h][ks][db],
                            vRow + bo + h * 2560 + db * 1280 + ks * 32);

        GROUP_BAR64(1 + p);

        // ---- full denominators (HADD2) -> rcp (2x f32 MUFU, repacked) ----
        uint32_t rcph[4][2];
#pragma unroll
        for (int nf = 0; nf < 4; nf++) {
            uint32_t q0 = *(uint32_t*)(pdB + (g)     * 80 + (nf * 8 + 2 * t4) * 2);
            uint32_t q1 = *(uint32_t*)(pdB + (g + 8) * 80 + (nf * 8 + 2 * t4) * 2);
            rcph[nf][0] = hrcp2(hadd2(pd2[nf][0], q0));
            rcph[nf][1] = hrcp2(hadd2(pd2[nf][1], q1));
        }

        // ---- O += W V (W = eh * rcph via HMUL2; V from smem as B-frags) ----
#pragma unroll
        for (int h = 0; h < 4; h++) {
#pragma unroll
            for (int ks = 0; ks < 2; ks++) {
                uint32_t wfrag[4];
                wfrag[0] = hmul2(eh[h][2 * ks][0],     rcph[2 * ks][0]);
                wfrag[1] = hmul2(eh[h][2 * ks][1],     rcph[2 * ks][1]);
                wfrag[2] = hmul2(eh[h][2 * ks + 1][0], rcph[2 * ks + 1][0]);
                wfrag[3] = hmul2(eh[h][2 * ks + 1][1], rcph[2 * ks + 1][1]);
#pragma unroll
                for (int db = 0; db < 2; db++) {
                    uint32_t vb[4];
                    if (h < 2) {
                        vb[0] = vb01[h][ks][db][0]; vb[1] = vb01[h][ks][db][1];
                        vb[2] = vb01[h][ks][db][2]; vb[3] = vb01[h][ks][db][3];
                    } else {
                        ldsm_x4(vb, vRow + bo + h * 2560 + db * 1280 + ks * 32);
                    }
                    mma16816(oacc[h][db * 2 + 0], wfrag, vb + 0);
                    mma16816(oacc[h][db * 2 + 1], wfrag, vb + 2);
                }
            }
        }
    }

    // ---- epilogue: scrambled flat-reshape layout, fp16 ----
#pragma unroll
    for (int h = 0; h < 4; h++) {
        const int gh = wip * 4 + h;
        __half* ob = af + ((size_t)(b * 256 + gh * 32 + qt * 2 + (p >> 1))) * 1024
                     + (p & 1) * 512;
#pragma unroll
        for (int nd = 0; nd < 4; nd++) {
#pragma unroll
            for (int rh = 0; rh < 2; rh++) {
                int col = (g + 8 * rh) * 32 + nd * 8 + 2 * t4;
                *(uint32_t*)(ob + col) =
                    pack_h2(oacc[h][nd][rh * 2 + 0], oacc[h][nd][rh * 2 + 1]);
            }
        }
    }
}

// ---------------------------------------------------------------------------
extern "C" void kernel_launch(void* const* d_in, const int* in_sizes, int n_in,
                              void* d_out, int out_size)
{
    const float* x      = (const float*)d_in[0];   // [8,512,32,32]
    const float* w_qkv  = (const float*)d_in[1];   // [768,512]
    const float* b_qkv  = (const float*)d_in[2];   // [768]
    const float* w_attn = (const float*)d_in[3];   // [512,256]
    const float* b_attn = (const float*)d_in[4];   // [512]
    float* out = (float*)d_out;                    // [8,512,32,32]

    void *xh, *wqh, *wah, *qkvp, *afp;
    cudaGetSymbolAddress(&xh,   g_xh);
    cudaGetSymbolAddress(&wqh,  g_wqkvh);
    cudaGetSymbolAddress(&wah,  g_wattnh);
    cudaGetSymbolAddress(&qkvp, g_qkvh);
    cudaGetSymbolAddress(&afp,  g_afh);

    cudaFuncSetAttribute((const void*)gemm_mma<768, 512, 256, __half>,
                         cudaFuncAttributeMaxDynamicSharedMemorySize, GEMM_SMEM);
    cudaFuncSetAttribute((const void*)gemm_mma<512, 256, 0, float>,
                         cudaFuncAttributeMaxDynamicSharedMemorySize, GEMM_SMEM);
    cudaFuncSetAttribute((const void*)attn_mma,
                         cudaFuncAttributeMaxDynamicSharedMemorySize, ATTN_SMEM);

    // 0) fused fp32 -> fp16 conversion (x, w_qkv, w_attn)
    f2h_all<<<(N4_ALL + 255) / 256, 256>>>(x, w_qkv, w_attn,
                                           (__half*)xh, (__half*)wqh, (__half*)wah);

    // 1) QKV projection; q rows pre-scaled by dkh^-0.5 * log2(e) so the
    //    attention exp is a bare ex2.
    gemm_mma<768, 512, 256, __half><<<dim3(8, 6, BATCH), 256, GEMM_SMEM>>>(
        (const __half*)wqh, (const __half*)xh, b_qkv, (__half*)qkvp,
        0.17677669529663687f * 1.4426950408889634f);

    // 2) fp16 fused attention, packed-fp16 MUFU softmax
    attn_mma<<<dim3(16, BATCH), 256, ATTN_SMEM>>>((const __half*)qkvp,
                                                  (__half*)afp);

    // 3) output projection (all-fp16 mma; fp32 output)
    gemm_mma<512, 256, 0, float><<<dim3(8, 4, BATCH), 256, GEMM_SMEM>>>(
        (const __half*)wah, (const __half*)afp, b_attn, out, 1.0f);
}